// round 5
// baseline (speedup 1.0000x reference)
#include <cuda_runtime.h>
#include <stdint.h>
#include <math.h>

// Problem constants
#define BATCH 2
#define TSEQ  1024
#define HDIM  1024
#define NTOK  (BATCH*TSEQ)     // 2048
#define NHEAD 16
#define NKVH  4
#define HEADD 64
#define NEXP  64
#define TOPK  8
#define IDIM  512

// ---------------- scratch (device globals; no allocations allowed) ----------
__device__ __align__(256) float g_h[NTOK*HDIM];
__device__ __align__(256) float g_q[NTOK*NHEAD*HEADD];
__device__ __align__(256) float g_k[NTOK*NKVH*HEADD];
__device__ __align__(256) float g_v[NTOK*NKVH*HEADD];
__device__ __align__(256) float g_ao[NTOK*HDIM];
__device__ __align__(256) float g_f[NTOK*HDIM];
__device__ int   g_cnt[NEXP];
__device__ int   g_elist[NEXP*NTOK];
__device__ float g_escore[NEXP*NTOK];
__device__ __align__(256) float g_gbuf[(size_t)NEXP*NTOK*IDIM];

// ---------------- helpers ----------------------------------------------------
__device__ __forceinline__ uint32_t ldcvt(const float* p) {
    uint32_t u;
    asm("cvt.rna.tf32.f32 %0, %1;" : "=r"(u) : "f"(*p));
    return u;
}

__device__ __forceinline__ void mma8(float* c, const uint32_t* a, const uint32_t* b) {
    asm volatile(
        "mma.sync.aligned.m16n8k8.row.col.f32.tf32.tf32.f32 "
        "{%0,%1,%2,%3}, {%4,%5,%6,%7}, {%8,%9}, {%0,%1,%2,%3};"
        : "+f"(c[0]), "+f"(c[1]), "+f"(c[2]), "+f"(c[3])
        : "r"(a[0]), "r"(a[1]), "r"(a[2]), "r"(a[3]), "r"(b[0]), "r"(b[1]));
}

__device__ __forceinline__ void cp16(uint32_t dst, const void* src, int sz) {
    asm volatile("cp.async.cg.shared.global [%0], [%1], 16, %2;"
                 :: "r"(dst), "l"(src), "r"(sz));
}

// ---------------- rmsnorm ---------------------------------------------------
__global__ void rmsnorm_kernel(const float* __restrict__ x,
                               const float* __restrict__ w,
                               float* __restrict__ o) {
    int row = blockIdx.x;
    const float* xr = x + (size_t)row * HDIM;
    __shared__ float red[256];
    float s = 0.f;
    for (int i = threadIdx.x; i < HDIM; i += 256) { float v = xr[i]; s += v * v; }
    red[threadIdx.x] = s;
    __syncthreads();
    for (int st = 128; st > 0; st >>= 1) {
        if (threadIdx.x < st) red[threadIdx.x] += red[threadIdx.x + st];
        __syncthreads();
    }
    float inv = rsqrtf(red[0] / (float)HDIM + 1e-6f);
    for (int i = threadIdx.x; i < HDIM; i += 256)
        o[(size_t)row * HDIM + i] = xr[i] * inv * w[i];
}

// ---------------- tf32 tensor-core GEMM, cp.async 3-stage pipeline ----------
// 128x128x16 tile, 256 threads (8 warps as 2x4, each warp 64x32 via m16n8k8).
// As: [m][k] rows padded to 20 floats (16B-aligned, conflict-free frag loads)
// Bs: [k][n] rows padded to 132 floats
// MODE 0: C = A@B (+R), guards on N (router N=64)
// MODE 1: MoE gate: gathered A rows; C -> gbuf
// MODE 2: MoE up:   gathered A; epilogue: gb = silu(gb) * acc * score
// MODE 3: MoE down: A = gbuf slice; epilogue: atomicAdd into out
#define AP 20
#define BP 132
#define ASZ (128*AP)
#define BSZ (16*BP)
#define STAGES 3
#define GEMM_SMEM ((STAGES*(ASZ+BSZ))*4 + 128*4)

template<int MODE>
__launch_bounds__(256, 2)
__global__ void mma_gemm(const float* __restrict__ A, const float* __restrict__ B,
                         const float* __restrict__ R, float* __restrict__ C,
                         int M, int N, int K,
                         const int* __restrict__ cnt, const int* __restrict__ elist,
                         const float* __restrict__ escore) {
    extern __shared__ float sh[];
    float* As = sh;
    float* Bs = sh + STAGES * ASZ;
    int* rows = (int*)(Bs + STAGES * BSZ);

    const int t = threadIdx.x;
    int e = 0, c = M;
    const int t0 = blockIdx.y * 128;
    const int by = blockIdx.y * 128;

    if (MODE >= 1) {
        e = blockIdx.z;
        c = cnt[e];
        if (t0 >= c) return;
        B += (size_t)e * K * N;
        if (MODE <= 2) {
            if (t < 128) {
                int tr = t0 + t;
                rows[t] = elist[e * NTOK + (tr < c ? tr : c - 1)];
            }
        } else {
            A += (size_t)e * NTOK * K;
        }
    }
    if (MODE == 1 || MODE == 2) __syncthreads();

    const int bx = blockIdx.x * 128;
    const int lane = t & 31, warp = t >> 5;
    const int lr = lane >> 2, lq = lane & 3;
    const int m0w = (warp & 1) * 64, n0w = (warp >> 1) * 32;

    const uint32_t sAu = (uint32_t)__cvta_generic_to_shared(As);
    const uint32_t sBu = (uint32_t)__cvta_generic_to_shared(Bs);

    float acc[4][4][4] = {};
    const int KT = K / 16;

    auto issue = [&](int buf, int k0) {
        uint32_t dA = sAu + buf * ASZ * 4;
        uint32_t dB = sBu + buf * BSZ * 4;
        #pragma unroll
        for (int i = 0; i < 2; i++) {
            int f = t * 2 + i;
            int r = f >> 2, seg = f & 3;     // A: 128 rows x 4 16B-segments
            int gr;
            if (MODE == 0) gr = by + r;
            else if (MODE == 3) gr = t0 + r;
            else gr = rows[r];
            cp16(dA + (r * AP + seg * 4) * 4, A + (size_t)gr * K + k0 + seg * 4, 16);
            int kr = f >> 5, sg = f & 31;    // B: 16 rows x 32 16B-segments
            int col = bx + sg * 4;
            const float* srcB = B + (size_t)(k0 + kr) * N + (col < N ? col : 0);
            cp16(dB + (kr * BP + sg * 4) * 4, srcB, col < N ? 16 : 0);
        }
    };

    #pragma unroll
    for (int s = 0; s < STAGES - 1; s++) {
        issue(s, s * 16);
        asm volatile("cp.async.commit_group;");
    }
    for (int it = 0; it < KT; it++) {
        if (it + STAGES - 1 < KT) issue((it + STAGES - 1) % STAGES, (it + STAGES - 1) * 16);
        asm volatile("cp.async.commit_group;");
        asm volatile("cp.async.wait_group 2;");
        __syncthreads();
        const float* Ab = As + (it % STAGES) * ASZ;
        const float* Bb = Bs + (it % STAGES) * BSZ;
        #pragma unroll
        for (int ks = 0; ks < 2; ks++) {
            const int kk = ks * 8;
            uint32_t af[4][4], bf[4][2];
            #pragma unroll
            for (int mt = 0; mt < 4; mt++) {
                int m = m0w + mt * 16 + lr;
                af[mt][0] = ldcvt(&Ab[m * AP + kk + lq]);
                af[mt][1] = ldcvt(&Ab[(m + 8) * AP + kk + lq]);
                af[mt][2] = ldcvt(&Ab[m * AP + kk + lq + 4]);
                af[mt][3] = ldcvt(&Ab[(m + 8) * AP + kk + lq + 4]);
            }
            #pragma unroll
            for (int nt = 0; nt < 4; nt++) {
                int n = n0w + nt * 8 + lr;
                bf[nt][0] = ldcvt(&Bb[(kk + lq) * BP + n]);
                bf[nt][1] = ldcvt(&Bb[(kk + lq + 4) * BP + n]);
            }
            #pragma unroll
            for (int mt = 0; mt < 4; mt++)
                #pragma unroll
                for (int nt = 0; nt < 4; nt++)
                    mma8(acc[mt][nt], af[mt], bf[nt]);
        }
        __syncthreads();
    }

    // epilogue
    #pragma unroll
    for (int mt = 0; mt < 4; mt++)
        #pragma unroll
        for (int i = 0; i < 2; i++) {
            int r = m0w + mt * 16 + lr + i * 8;
            #pragma unroll
            for (int nt = 0; nt < 4; nt++) {
                int col = bx + n0w + nt * 8 + lq * 2;
                float v0 = acc[mt][nt][i * 2 + 0];
                float v1 = acc[mt][nt][i * 2 + 1];
                if (MODE == 0) {
                    if (col < N) {
                        int gr = by + r;
                        size_t o = (size_t)gr * N + col;
                        if (R) { v0 += R[o]; v1 += R[o + 1]; }
                        C[o] = v0; C[o + 1] = v1;
                    }
                } else {
                    int tr = t0 + r;
                    if (tr < c) {
                        if (MODE == 1) {
                            size_t o = ((size_t)e * NTOK + tr) * N + col;
                            C[o] = v0; C[o + 1] = v1;
                        } else if (MODE == 2) {
                            size_t o = ((size_t)e * NTOK + tr) * N + col;
                            float sc = escore[e * NTOK + tr];
                            float g0 = C[o], g1 = C[o + 1];
                            C[o]     = g0 / (1.f + expf(-g0)) * v0 * sc;
                            C[o + 1] = g1 / (1.f + expf(-g1)) * v1 * sc;
                        } else {
                            int n = elist[e * NTOK + tr];
                            atomicAdd(&C[(size_t)n * N + col], v0);
                            atomicAdd(&C[(size_t)n * N + col + 1], v1);
                        }
                    }
                }
            }
        }
}

// ---------------- RoPE (in place) -------------------------------------------
__global__ void rope_kernel(float* __restrict__ q, const float* __restrict__ cs,
                            const float* __restrict__ sn, int nheads) {
    int idx = blockIdx.x * blockDim.x + threadIdx.x;
    int total = NTOK * nheads * 32;
    if (idx >= total) return;
    int d  = idx & 31;
    int hh = (idx >> 5) % nheads;
    int n  = idx / (32 * nheads);
    int tp = n % TSEQ;
    float c0 = cs[tp * HEADD + d],      s0 = sn[tp * HEADD + d];
    float c1 = cs[tp * HEADD + d + 32], s1 = sn[tp * HEADD + d + 32];
    float* base = q + ((size_t)n * nheads + hh) * HEADD;
    float v0 = base[d], v1 = base[d + 32];
    base[d]      = v0 * c0 - v1 * s0;
    base[d + 32] = v1 * c1 + v0 * s1;
}

// ---------------- tiled causal flash attention ------------------------------
__global__ void attn_kernel(const float* __restrict__ Q, const float* __restrict__ Kg,
                            const float* __restrict__ Vg, float* __restrict__ O) {
    extern __shared__ float sm[];
    float* Qs = sm;                       // [64][65]
    float* Ks = sm + 64 * 65;             // [64][65]
    float* Vs = sm + 2 * 64 * 65;         // [64][68]
    float* Ss = sm + 2 * 64 * 65 + 64 * 68; // [64][65]
    __shared__ float m_s[64], l_s[64], corr_s[64];

    int qt = (int)gridDim.x - 1 - (int)blockIdx.x;
    int h = blockIdx.y, b = blockIdx.z;
    int kvh = h >> 2;
    int t = threadIdx.x, ty = t >> 4, tx = t & 15;
    int q0 = ty * 4, d0c = tx * 4;

    {
        int r = t >> 2, d0 = (t & 3) * 16;
        int n = b * TSEQ + qt * 64 + r;
        const float* src = Q + ((size_t)n * NHEAD + h) * 64 + d0;
        #pragma unroll
        for (int j = 0; j < 16; j += 4) {
            float4 v = *(const float4*)(src + j);
            Qs[r * 65 + d0 + j]     = v.x;
            Qs[r * 65 + d0 + j + 1] = v.y;
            Qs[r * 65 + d0 + j + 2] = v.z;
            Qs[r * 65 + d0 + j + 3] = v.w;
        }
    }
    if (t < 64) { m_s[t] = -1e30f; l_s[t] = 0.f; }

    float o[4][4];
    #pragma unroll
    for (int i = 0; i < 4; i++)
        #pragma unroll
        for (int j = 0; j < 4; j++) o[i][j] = 0.f;

    for (int kt = 0; kt <= qt; kt++) {
        __syncthreads();
        {
            int r = t >> 2, dd0 = (t & 3) * 16;
            int kn = b * TSEQ + kt * 64 + r;
            const float* ks = Kg + ((size_t)kn * NKVH + kvh) * 64 + dd0;
            const float* vs = Vg + ((size_t)kn * NKVH + kvh) * 64 + dd0;
            #pragma unroll
            for (int j = 0; j < 16; j += 4) {
                float4 kv = *(const float4*)(ks + j);
                Ks[r * 65 + dd0 + j]     = kv.x;
                Ks[r * 65 + dd0 + j + 1] = kv.y;
                Ks[r * 65 + dd0 + j + 2] = kv.z;
                Ks[r * 65 + dd0 + j + 3] = kv.w;
                float4 vv = *(const float4*)(vs + j);
                *(float4*)&Vs[r * 68 + dd0 + j] = vv;
            }
        }
        __syncthreads();
        float s4[4][4];
        #pragma unroll
        for (int i = 0; i < 4; i++)
            #pragma unroll
            for (int j = 0; j < 4; j++) s4[i][j] = 0.f;
        for (int d = 0; d < 64; d++) {
            float a[4], bb[4];
            #pragma unroll
            for (int i = 0; i < 4; i++) a[i] = Qs[(q0 + i) * 65 + d];
            #pragma unroll
            for (int j = 0; j < 4; j++) bb[j] = Ks[(d0c + j) * 65 + d];
            #pragma unroll
            for (int i = 0; i < 4; i++)
                #pragma unroll
                for (int j = 0; j < 4; j++) s4[i][j] += a[i] * bb[j];
        }
        #pragma unroll
        for (int i = 0; i < 4; i++)
            #pragma unroll
            for (int j = 0; j < 4; j++) {
                int kglob = kt * 64 + d0c + j, qglob = qt * 64 + q0 + i;
                Ss[(q0 + i) * 65 + d0c + j] =
                    (kglob <= qglob) ? s4[i][j] * 0.125f : -1e30f;
            }
        __syncthreads();
        if (t < 64) {
            float mx = -1e30f;
            for (int k = 0; k < 64; k++) mx = fmaxf(mx, Ss[t * 65 + k]);
            float newm = fmaxf(m_s[t], mx);
            float corr = expf(m_s[t] - newm);
            float sum = 0.f;
            for (int k = 0; k < 64; k++) sum += expf(Ss[t * 65 + k] - newm);
            l_s[t] = l_s[t] * corr + sum;
            m_s[t] = newm;
            corr_s[t] = corr;
        }
        __syncthreads();
        #pragma unroll
        for (int i = 0; i < 4; i++) {
            float nm = m_s[q0 + i];
            float cr = corr_s[q0 + i];
            #pragma unroll
            for (int j = 0; j < 4; j++) {
                float p = expf(Ss[(q0 + i) * 65 + d0c + j] - nm);
                Ss[(q0 + i) * 65 + d0c + j] = p;
                o[i][j] *= cr;
            }
        }
        __syncthreads();
        for (int k = 0; k < 64; k++) {
            float a[4];
            #pragma unroll
            for (int i = 0; i < 4; i++) a[i] = Ss[(q0 + i) * 65 + k];
            float4 bv = *(const float4*)&Vs[k * 68 + d0c];
            #pragma unroll
            for (int i = 0; i < 4; i++) {
                o[i][0] += a[i] * bv.x;
                o[i][1] += a[i] * bv.y;
                o[i][2] += a[i] * bv.z;
                o[i][3] += a[i] * bv.w;
            }
        }
    }
    #pragma unroll
    for (int i = 0; i < 4; i++) {
        float inv = 1.f / l_s[q0 + i];
        int n = b * TSEQ + qt * 64 + q0 + i;
        #pragma unroll
        for (int j = 0; j < 4; j++)
            O[(size_t)n * HDIM + h * 64 + d0c + j] = o[i][j] * inv;
    }
}

// ---------------- router ----------------------------------------------------
__global__ void zero_cnt_kernel(int* __restrict__ cnt) {
    if (threadIdx.x < NEXP) cnt[threadIdx.x] = 0;
}

__global__ void router_topk_kernel(const float* __restrict__ logits,
                                   int* __restrict__ cnt, int* __restrict__ elist,
                                   float* __restrict__ escore) {
    int n = blockIdx.x * blockDim.x + threadIdx.x;
    if (n >= NTOK) return;
    float lg[NEXP];
    for (int e = 0; e < NEXP; e++) lg[e] = logits[(size_t)n * NEXP + e];
    int sel[TOPK]; float sv[TOPK];
    for (int k = 0; k < TOPK; k++) {
        float best = -1e30f; int bi = 0;
        for (int e = 0; e < NEXP; e++)
            if (lg[e] > best) { best = lg[e]; bi = e; }
        sel[k] = bi; sv[k] = best; lg[bi] = -1e30f;
    }
    float mx = sv[0];
    float ssum = 0.f;
    for (int k = 0; k < TOPK; k++) { sv[k] = expf(sv[k] - mx); ssum += sv[k]; }
    for (int k = 0; k < TOPK; k++) {
        int e = sel[k];
        int pos = atomicAdd(&cnt[e], 1);
        elist[e * NTOK + pos]  = n;
        escore[e * NTOK + pos] = sv[k] / ssum;
    }
}

// ---------------- launch ----------------------------------------------------
extern "C" void kernel_launch(void* const* d_in, const int* in_sizes, int n_in,
                              void* d_out, int out_size) {
    const float* x    = (const float*)d_in[0];
    const float* cosb = (const float*)d_in[1];
    const float* sinb = (const float*)d_in[2];
    const float* ln1  = (const float*)d_in[3];
    const float* ln2  = (const float*)d_in[4];
    const float* Wq   = (const float*)d_in[5];
    const float* Wk   = (const float*)d_in[6];
    const float* Wv   = (const float*)d_in[7];
    const float* Wo   = (const float*)d_in[8];
    const float* Wr   = (const float*)d_in[9];
    const float* Wg   = (const float*)d_in[10];
    const float* Wu   = (const float*)d_in[11];
    const float* Wd   = (const float*)d_in[12];
    float* out = (float*)d_out;
    float* rl  = out + (size_t)NTOK * HDIM;

    float *h, *q, *k, *v, *ao, *f, *gb, *es;
    int *cnt, *el;
    cudaGetSymbolAddress((void**)&h,   g_h);
    cudaGetSymbolAddress((void**)&q,   g_q);
    cudaGetSymbolAddress((void**)&k,   g_k);
    cudaGetSymbolAddress((void**)&v,   g_v);
    cudaGetSymbolAddress((void**)&ao,  g_ao);
    cudaGetSymbolAddress((void**)&f,   g_f);
    cudaGetSymbolAddress((void**)&gb,  g_gbuf);
    cudaGetSymbolAddress((void**)&es,  g_escore);
    cudaGetSymbolAddress((void**)&cnt, g_cnt);
    cudaGetSymbolAddress((void**)&el,  g_elist);

    const int ATTN_SMEM = (2 * 64 * 65 + 64 * 68 + 64 * 65) * 4;
    cudaFuncSetAttribute(attn_kernel, cudaFuncAttributeMaxDynamicSharedMemorySize,
                         ATTN_SMEM);
    cudaFuncSetAttribute(mma_gemm<0>, cudaFuncAttributeMaxDynamicSharedMemorySize, GEMM_SMEM);
    cudaFuncSetAttribute(mma_gemm<1>, cudaFuncAttributeMaxDynamicSharedMemorySize, GEMM_SMEM);
    cudaFuncSetAttribute(mma_gemm<2>, cudaFuncAttributeMaxDynamicSharedMemorySize, GEMM_SMEM);
    cudaFuncSetAttribute(mma_gemm<3>, cudaFuncAttributeMaxDynamicSharedMemorySize, GEMM_SMEM);

    // 1. h = rmsnorm(x, ln1_w)
    rmsnorm_kernel<<<NTOK, 256>>>(x, ln1, h);
    // 2. QKV projections (tf32 mma, cp.async pipelined)
    mma_gemm<0><<<dim3(8, 16), 256, GEMM_SMEM>>>(h, Wq, nullptr, q, NTOK, 1024, 1024, nullptr, nullptr, nullptr);
    mma_gemm<0><<<dim3(2, 16), 256, GEMM_SMEM>>>(h, Wk, nullptr, k, NTOK,  256, 1024, nullptr, nullptr, nullptr);
    mma_gemm<0><<<dim3(2, 16), 256, GEMM_SMEM>>>(h, Wv, nullptr, v, NTOK,  256, 1024, nullptr, nullptr, nullptr);
    // 3. RoPE
    rope_kernel<<<(NTOK * NHEAD * 32 + 255) / 256, 256>>>(q, cosb, sinb, NHEAD);
    rope_kernel<<<(NTOK * NKVH  * 32 + 255) / 256, 256>>>(k, cosb, sinb, NKVH);
    // 4. attention
    attn_kernel<<<dim3(TSEQ / 64, NHEAD, BATCH), 256, ATTN_SMEM>>>(q, k, v, ao);
    // 5. x1 = x + ao@Wo
    mma_gemm<0><<<dim3(8, 16), 256, GEMM_SMEM>>>(ao, Wo, x, out, NTOK, 1024, 1024, nullptr, nullptr, nullptr);
    // 6. f = rmsnorm(x1, ln2_w)
    rmsnorm_kernel<<<NTOK, 256>>>(out, ln2, f);
    // 7. router logits
    mma_gemm<0><<<dim3(1, 16), 256, GEMM_SMEM>>>(f, Wr, nullptr, rl, NTOK, NEXP, 1024, nullptr, nullptr, nullptr);
    // 8-9. top-k + expert lists
    zero_cnt_kernel<<<1, 64>>>(cnt);
    router_topk_kernel<<<NTOK / 256, 256>>>(rl, cnt, el, es);
    // 10a. gate GEMM -> gb
    mma_gemm<1><<<dim3(IDIM / 128, NTOK / 128, NEXP), 256, GEMM_SMEM>>>(f, Wg, nullptr, gb, NTOK, IDIM, 1024, cnt, el, es);
    // 10b. up GEMM, fused silu(gate)*up*score -> gb
    mma_gemm<2><<<dim3(IDIM / 128, NTOK / 128, NEXP), 256, GEMM_SMEM>>>(f, Wu, nullptr, gb, NTOK, IDIM, 1024, cnt, el, es);
    // 11. down GEMM + scatter-add onto residual in d_out
    mma_gemm<3><<<dim3(HDIM / 128, NTOK / 128, NEXP), 256, GEMM_SMEM>>>(gb, Wd, nullptr, out, NTOK, HDIM, IDIM, cnt, el, es);
}

// round 6
// speedup vs baseline: 1.2907x; 1.2907x over previous
#include <cuda_runtime.h>
#include <stdint.h>
#include <math.h>

// Problem constants
#define BATCH 2
#define TSEQ  1024
#define HDIM  1024
#define NTOK  (BATCH*TSEQ)     // 2048
#define NHEAD 16
#define NKVH  4
#define HEADD 64
#define NEXP  64
#define TOPK  8
#define IDIM  512

// ---------------- scratch (device globals; no allocations allowed) ----------
__device__ __align__(256) float g_h[NTOK*HDIM];
__device__ __align__(256) float g_q[NTOK*NHEAD*HEADD];
__device__ __align__(256) float g_k[NTOK*NKVH*HEADD];
__device__ __align__(256) float g_v[NTOK*NKVH*HEADD];
__device__ __align__(256) float g_ao[NTOK*HDIM];
__device__ __align__(256) float g_f[NTOK*HDIM];
__device__ int   g_cnt[NEXP];
__device__ int   g_elist[NEXP*NTOK];
__device__ float g_escore[NEXP*NTOK];
__device__ __align__(256) float g_gbuf[(size_t)NEXP*NTOK*IDIM];

// ---------------- helpers ----------------------------------------------------
__device__ __forceinline__ float tf32r(float x) {
    uint32_t u;
    asm("cvt.rna.tf32.f32 %0, %1;" : "=r"(u) : "f"(x));
    return __uint_as_float(u);
}
__device__ __forceinline__ uint32_t ldcvt(const float* p) {
    uint32_t u;
    asm("cvt.rna.tf32.f32 %0, %1;" : "=r"(u) : "f"(*p));
    return u;
}
// k-permutation within each 16-element group: pos 4a+b -> 4b+a (self-inverse)
__device__ __forceinline__ int permc(int i) {
    return (i & ~15) | (((i & 3) << 2) | ((i >> 2) & 3));
}

__device__ __forceinline__ void mma8(float* c, const uint32_t* a, const uint32_t* b) {
    asm volatile(
        "mma.sync.aligned.m16n8k8.row.col.f32.tf32.tf32.f32 "
        "{%0,%1,%2,%3}, {%4,%5,%6,%7}, {%8,%9}, {%0,%1,%2,%3};"
        : "+f"(c[0]), "+f"(c[1]), "+f"(c[2]), "+f"(c[3])
        : "r"(a[0]), "r"(a[1]), "r"(a[2]), "r"(a[3]), "r"(b[0]), "r"(b[1]));
}

__device__ __forceinline__ void cp16(uint32_t dst, const void* src, int sz) {
    asm volatile("cp.async.cg.shared.global [%0], [%1], 16, %2;"
                 :: "r"(dst), "l"(src), "r"(sz));
}

// ---------------- rmsnorm (writes tf32-rounded, k-permuted) ------------------
__global__ void rmsnorm_kernel(const float* __restrict__ x,
                               const float* __restrict__ w,
                               float* __restrict__ o) {
    int row = blockIdx.x;
    const float* xr = x + (size_t)row * HDIM;
    __shared__ float red[256];
    float s = 0.f;
    for (int i = threadIdx.x; i < HDIM; i += 256) { float v = xr[i]; s += v * v; }
    red[threadIdx.x] = s;
    __syncthreads();
    for (int st = 128; st > 0; st >>= 1) {
        if (threadIdx.x < st) red[threadIdx.x] += red[threadIdx.x + st];
        __syncthreads();
    }
    float inv = rsqrtf(red[0] / (float)HDIM + 1e-6f);
    for (int i = threadIdx.x; i < HDIM; i += 256)
        o[(size_t)row * HDIM + permc(i)] = tf32r(xr[i] * inv * w[i]);
}

// ---------------- tf32 tensor-core GEMM, cp.async 3-stage pipeline ----------
// 128x128x16 tile, 256 threads (8 warps as 2x4, each warp 64x32 via m16n8k8).
// A operand MUST be tf32-pre-rounded and k-permuted (all producers do this).
// As: [m][k-permuted] rows padded to 20; thread A-frags = 2 float4 per mt.
// Bs: [k][n] rows padded to 136 (conflict-free scalar frag loads)
// MODE 0: C = A@B (+R), guards on N (router N=64)
// MODE 1: MoE gate: gathered A rows; C -> gbuf (plain layout)
// MODE 2: MoE up:   gathered A; epilogue: gb = silu(gb)*acc*score, stored
//                   tf32+permuted (gbuf becomes A of down GEMM)
// MODE 3: MoE down: A = gbuf slice; epilogue: atomicAdd into out
// MODE 4: fused QKV: B/C routed per 128-col tile among Wq/Wk/Wv -> q/k/v
#define AP 20
#define BP 136
#define ASZ (128*AP)
#define BSZ (16*BP)
#define STAGES 3
#define GEMM_SMEM ((STAGES*(ASZ+BSZ))*4 + 128*4)

template<int MODE>
__launch_bounds__(256, 2)
__global__ void mma_gemm(const float* __restrict__ A, const float* __restrict__ B,
                         const float* __restrict__ R, float* __restrict__ C,
                         int M, int N, int K,
                         const int* __restrict__ cnt, const int* __restrict__ elist,
                         const float* __restrict__ escore,
                         const float* __restrict__ B2, const float* __restrict__ B3,
                         float* __restrict__ C2, float* __restrict__ C3) {
    extern __shared__ float sh[];
    float* As = sh;
    float* Bs = sh + STAGES * ASZ;
    int* rows = (int*)(Bs + STAGES * BSZ);

    const int t = threadIdx.x;
    int e = 0, c = M;
    const int t0 = blockIdx.y * 128;
    const int by = t0;
    const int bx = blockIdx.x * 128;

    // B / C routing
    const float* Bp = B; int Ns = N; int bcol = bx;
    float* Cp = C; int cstr = N; int ccol = bx;
    if (MODE == 4) {
        if (bx < 1024)      { Bp = B;  Ns = 1024; bcol = bx;        Cp = C;  cstr = 1024; ccol = bx; }
        else if (bx < 1280) { Bp = B2; Ns = 256;  bcol = bx - 1024; Cp = C2; cstr = 256;  ccol = bx - 1024; }
        else                { Bp = B3; Ns = 256;  bcol = bx - 1280; Cp = C3; cstr = 256;  ccol = bx - 1280; }
    }
    if (MODE >= 1 && MODE <= 3) {
        e = blockIdx.z;
        c = cnt[e];
        if (t0 >= c) return;
        Bp = B + (size_t)e * K * N;
        if (MODE <= 2) {
            if (t < 128) {
                int tr = t0 + t;
                rows[t] = elist[e * NTOK + (tr < c ? tr : c - 1)];
            }
        } else {
            A += (size_t)e * NTOK * K;
        }
    }
    if (MODE == 1 || MODE == 2) __syncthreads();

    const int lane = t & 31, warp = t >> 5;
    const int lr = lane >> 2, lq = lane & 3;
    const int m0w = (warp & 1) * 64, n0w = (warp >> 1) * 32;

    const uint32_t sAu = (uint32_t)__cvta_generic_to_shared(As);
    const uint32_t sBu = (uint32_t)__cvta_generic_to_shared(Bs);

    float acc[4][4][4] = {};
    const int KT = K / 16;

    auto issue = [&](int buf, int k0) {
        uint32_t dA = sAu + buf * ASZ * 4;
        uint32_t dB = sBu + buf * BSZ * 4;
        #pragma unroll
        for (int i = 0; i < 2; i++) {
            int f = t * 2 + i;
            int r = f >> 2, seg = f & 3;     // A: 128 rows x 4 16B-segments
            int gr;
            if (MODE == 0 || MODE == 4) gr = by + r;
            else if (MODE == 3) gr = t0 + r;
            else gr = rows[r];
            cp16(dA + (r * AP + seg * 4) * 4, A + (size_t)gr * K + k0 + seg * 4, 16);
            int kr = f >> 5, sg = f & 31;    // B: 16 rows x 32 16B-segments
            int col = bcol + sg * 4;
            const float* srcB = Bp + (size_t)(k0 + kr) * Ns + (col < Ns ? col : 0);
            cp16(dB + (kr * BP + sg * 4) * 4, srcB, col < Ns ? 16 : 0);
        }
    };

    #pragma unroll
    for (int s = 0; s < STAGES - 1; s++) {
        issue(s, s * 16);
        asm volatile("cp.async.commit_group;");
    }
    for (int it = 0; it < KT; it++) {
        if (it + STAGES - 1 < KT) issue((it + STAGES - 1) % STAGES, (it + STAGES - 1) * 16);
        asm volatile("cp.async.commit_group;");
        asm volatile("cp.async.wait_group 2;");
        __syncthreads();
        const float* Ab = As + (it % STAGES) * ASZ;
        const float* Bb = Bs + (it % STAGES) * BSZ;

        // A fragments: one float4 pair per mt covers both ks halves, no cvt
        uint32_t a0[4][4], a1[4][4];
        #pragma unroll
        for (int mt = 0; mt < 4; mt++) {
            int m = m0w + mt * 16 + lr;
            float4 va = *(const float4*)&Ab[m * AP + 4 * lq];
            float4 vb = *(const float4*)&Ab[(m + 8) * AP + 4 * lq];
            a0[mt][0] = __float_as_uint(va.x); a0[mt][1] = __float_as_uint(vb.x);
            a0[mt][2] = __float_as_uint(va.y); a0[mt][3] = __float_as_uint(vb.y);
            a1[mt][0] = __float_as_uint(va.z); a1[mt][1] = __float_as_uint(vb.z);
            a1[mt][2] = __float_as_uint(va.w); a1[mt][3] = __float_as_uint(vb.w);
        }
        uint32_t b0[4][2], b1[4][2];
        #pragma unroll
        for (int nt = 0; nt < 4; nt++) {
            int n = n0w + nt * 8 + lr;
            b0[nt][0] = ldcvt(&Bb[lq * BP + n]);
            b0[nt][1] = ldcvt(&Bb[(lq + 4) * BP + n]);
            b1[nt][0] = ldcvt(&Bb[(8 + lq) * BP + n]);
            b1[nt][1] = ldcvt(&Bb[(12 + lq) * BP + n]);
        }
        #pragma unroll
        for (int mt = 0; mt < 4; mt++)
            #pragma unroll
            for (int nt = 0; nt < 4; nt++) {
                mma8(acc[mt][nt], a0[mt], b0[nt]);
                mma8(acc[mt][nt], a1[mt], b1[nt]);
            }
        __syncthreads();
    }

    // ---------------- epilogue ----------------
    if (MODE == 2) {
        // pass 1: read gate (plain layout), combine into acc
        #pragma unroll
        for (int mt = 0; mt < 4; mt++)
            #pragma unroll
            for (int i = 0; i < 2; i++) {
                int r = m0w + mt * 16 + lr + i * 8;
                int tr = t0 + r;
                if (tr >= c) continue;
                float sc = escore[e * NTOK + tr];
                #pragma unroll
                for (int nt = 0; nt < 4; nt++) {
                    int col = bx + n0w + nt * 8 + lq * 2;
                    size_t o = ((size_t)e * NTOK + tr) * N + col;
                    float g0 = C[o], g1 = C[o + 1];
                    acc[mt][nt][i * 2]     = tf32r(g0 / (1.f + expf(-g0)) * acc[mt][nt][i * 2]     * sc);
                    acc[mt][nt][i * 2 + 1] = tf32r(g1 / (1.f + expf(-g1)) * acc[mt][nt][i * 2 + 1] * sc);
                }
            }
        __syncthreads();
        // pass 2: write permuted (gbuf becomes A of down GEMM)
        #pragma unroll
        for (int mt = 0; mt < 4; mt++)
            #pragma unroll
            for (int i = 0; i < 2; i++) {
                int r = m0w + mt * 16 + lr + i * 8;
                int tr = t0 + r;
                if (tr >= c) continue;
                #pragma unroll
                for (int nt = 0; nt < 4; nt++) {
                    int col = bx + n0w + nt * 8 + lq * 2;
                    int pc = permc(col);
                    size_t ob = ((size_t)e * NTOK + tr) * N;
                    C[ob + pc]     = acc[mt][nt][i * 2];
                    C[ob + pc + 4] = acc[mt][nt][i * 2 + 1];  // permc(col+1)=permc(col)+4
                }
            }
        return;
    }
    #pragma unroll
    for (int mt = 0; mt < 4; mt++)
        #pragma unroll
        for (int i = 0; i < 2; i++) {
            int r = m0w + mt * 16 + lr + i * 8;
            #pragma unroll
            for (int nt = 0; nt < 4; nt++) {
                int col = ccol + n0w + nt * 8 + lq * 2;
                float v0 = acc[mt][nt][i * 2 + 0];
                float v1 = acc[mt][nt][i * 2 + 1];
                if (MODE == 0 || MODE == 4) {
                    if (col < Ns) {
                        int gr = by + r;
                        size_t o = (size_t)gr * cstr + col;
                        if (MODE == 0 && R) { v0 += R[o]; v1 += R[o + 1]; }
                        Cp[o] = v0; Cp[o + 1] = v1;
                    }
                } else {
                    int tr = t0 + r;
                    if (tr < c) {
                        if (MODE == 1) {
                            size_t o = ((size_t)e * NTOK + tr) * N + (bx + n0w + nt * 8 + lq * 2);
                            C[o] = v0; C[o + 1] = v1;
                        } else {  // MODE 3
                            int n = elist[e * NTOK + tr];
                            int cc = bx + n0w + nt * 8 + lq * 2;
                            atomicAdd(&C[(size_t)n * N + cc], v0);
                            atomicAdd(&C[(size_t)n * N + cc + 1], v1);
                        }
                    }
                }
            }
        }
}

// ---------------- RoPE (in place) -------------------------------------------
__global__ void rope_kernel(float* __restrict__ q, const float* __restrict__ cs,
                            const float* __restrict__ sn, int nheads) {
    int idx = blockIdx.x * blockDim.x + threadIdx.x;
    int total = NTOK * nheads * 32;
    if (idx >= total) return;
    int d  = idx & 31;
    int hh = (idx >> 5) % nheads;
    int n  = idx / (32 * nheads);
    int tp = n % TSEQ;
    float c0 = cs[tp * HEADD + d],      s0 = sn[tp * HEADD + d];
    float c1 = cs[tp * HEADD + d + 32], s1 = sn[tp * HEADD + d + 32];
    float* base = q + ((size_t)n * nheads + hh) * HEADD;
    float v0 = base[d], v1 = base[d + 32];
    base[d]      = v0 * c0 - v1 * s0;
    base[d + 32] = v1 * c1 + v0 * s1;
}

// ---------------- tiled causal flash attention ------------------------------
// Output written tf32-rounded + k-permuted (feeds Wo GEMM as A).
__global__ void attn_kernel(const float* __restrict__ Q, const float* __restrict__ Kg,
                            const float* __restrict__ Vg, float* __restrict__ O) {
    extern __shared__ float sm[];
    float* Qs = sm;                       // [64][65]
    float* Ks = sm + 64 * 65;             // [64][65]
    float* Vs = sm + 2 * 64 * 65;         // [64][68]
    float* Ss = sm + 2 * 64 * 65 + 64 * 68; // [64][65]
    __shared__ float m_s[64], l_s[64], corr_s[64];

    int qt = (int)gridDim.x - 1 - (int)blockIdx.x;
    int h = blockIdx.y, b = blockIdx.z;
    int kvh = h >> 2;
    int t = threadIdx.x, ty = t >> 4, tx = t & 15;
    int q0 = ty * 4, d0c = tx * 4;

    {
        int r = t >> 2, d0 = (t & 3) * 16;
        int n = b * TSEQ + qt * 64 + r;
        const float* src = Q + ((size_t)n * NHEAD + h) * 64 + d0;
        #pragma unroll
        for (int j = 0; j < 16; j += 4) {
            float4 v = *(const float4*)(src + j);
            Qs[r * 65 + d0 + j]     = v.x;
            Qs[r * 65 + d0 + j + 1] = v.y;
            Qs[r * 65 + d0 + j + 2] = v.z;
            Qs[r * 65 + d0 + j + 3] = v.w;
        }
    }
    if (t < 64) { m_s[t] = -1e30f; l_s[t] = 0.f; }

    float o[4][4];
    #pragma unroll
    for (int i = 0; i < 4; i++)
        #pragma unroll
        for (int j = 0; j < 4; j++) o[i][j] = 0.f;

    for (int kt = 0; kt <= qt; kt++) {
        __syncthreads();
        {
            int r = t >> 2, dd0 = (t & 3) * 16;
            int kn = b * TSEQ + kt * 64 + r;
            const float* ks = Kg + ((size_t)kn * NKVH + kvh) * 64 + dd0;
            const float* vs = Vg + ((size_t)kn * NKVH + kvh) * 64 + dd0;
            #pragma unroll
            for (int j = 0; j < 16; j += 4) {
                float4 kv = *(const float4*)(ks + j);
                Ks[r * 65 + dd0 + j]     = kv.x;
                Ks[r * 65 + dd0 + j + 1] = kv.y;
                Ks[r * 65 + dd0 + j + 2] = kv.z;
                Ks[r * 65 + dd0 + j + 3] = kv.w;
                float4 vv = *(const float4*)(vs + j);
                *(float4*)&Vs[r * 68 + dd0 + j] = vv;
            }
        }
        __syncthreads();
        float s4[4][4];
        #pragma unroll
        for (int i = 0; i < 4; i++)
            #pragma unroll
            for (int j = 0; j < 4; j++) s4[i][j] = 0.f;
        for (int d = 0; d < 64; d++) {
            float a[4], bb[4];
            #pragma unroll
            for (int i = 0; i < 4; i++) a[i] = Qs[(q0 + i) * 65 + d];
            #pragma unroll
            for (int j = 0; j < 4; j++) bb[j] = Ks[(d0c + j) * 65 + d];
            #pragma unroll
            for (int i = 0; i < 4; i++)
                #pragma unroll
                for (int j = 0; j < 4; j++) s4[i][j] += a[i] * bb[j];
        }
        #pragma unroll
        for (int i = 0; i < 4; i++)
            #pragma unroll
            for (int j = 0; j < 4; j++) {
                int kglob = kt * 64 + d0c + j, qglob = qt * 64 + q0 + i;
                Ss[(q0 + i) * 65 + d0c + j] =
                    (kglob <= qglob) ? s4[i][j] * 0.125f : -1e30f;
            }
        __syncthreads();
        if (t < 64) {
            float mx = -1e30f;
            for (int k = 0; k < 64; k++) mx = fmaxf(mx, Ss[t * 65 + k]);
            float newm = fmaxf(m_s[t], mx);
            float corr = expf(m_s[t] - newm);
            float sum = 0.f;
            for (int k = 0; k < 64; k++) sum += expf(Ss[t * 65 + k] - newm);
            l_s[t] = l_s[t] * corr + sum;
            m_s[t] = newm;
            corr_s[t] = corr;
        }
        __syncthreads();
        #pragma unroll
        for (int i = 0; i < 4; i++) {
            float nm = m_s[q0 + i];
            float cr = corr_s[q0 + i];
            #pragma unroll
            for (int j = 0; j < 4; j++) {
                float p = expf(Ss[(q0 + i) * 65 + d0c + j] - nm);
                Ss[(q0 + i) * 65 + d0c + j] = p;
                o[i][j] *= cr;
            }
        }
        __syncthreads();
        for (int k = 0; k < 64; k++) {
            float a[4];
            #pragma unroll
            for (int i = 0; i < 4; i++) a[i] = Ss[(q0 + i) * 65 + k];
            float4 bv = *(const float4*)&Vs[k * 68 + d0c];
            #pragma unroll
            for (int i = 0; i < 4; i++) {
                o[i][0] += a[i] * bv.x;
                o[i][1] += a[i] * bv.y;
                o[i][2] += a[i] * bv.z;
                o[i][3] += a[i] * bv.w;
            }
        }
    }
    #pragma unroll
    for (int i = 0; i < 4; i++) {
        float inv = 1.f / l_s[q0 + i];
        int n = b * TSEQ + qt * 64 + q0 + i;
        #pragma unroll
        for (int j = 0; j < 4; j++)
            O[(size_t)n * HDIM + permc(h * 64 + d0c + j)] = tf32r(o[i][j] * inv);
    }
}

// ---------------- router ----------------------------------------------------
__global__ void zero_cnt_kernel(int* __restrict__ cnt) {
    if (threadIdx.x < NEXP) cnt[threadIdx.x] = 0;
}

__global__ void router_topk_kernel(const float* __restrict__ logits,
                                   int* __restrict__ cnt, int* __restrict__ elist,
                                   float* __restrict__ escore) {
    int n = blockIdx.x * blockDim.x + threadIdx.x;
    if (n >= NTOK) return;
    float lg[NEXP];
    for (int e = 0; e < NEXP; e++) lg[e] = logits[(size_t)n * NEXP + e];
    int sel[TOPK]; float sv[TOPK];
    for (int k = 0; k < TOPK; k++) {
        float best = -1e30f; int bi = 0;
        for (int e = 0; e < NEXP; e++)
            if (lg[e] > best) { best = lg[e]; bi = e; }
        sel[k] = bi; sv[k] = best; lg[bi] = -1e30f;
    }
    float mx = sv[0];
    float ssum = 0.f;
    for (int k = 0; k < TOPK; k++) { sv[k] = expf(sv[k] - mx); ssum += sv[k]; }
    for (int k = 0; k < TOPK; k++) {
        int e = sel[k];
        int pos = atomicAdd(&cnt[e], 1);
        elist[e * NTOK + pos]  = n;
        escore[e * NTOK + pos] = sv[k] / ssum;
    }
}

// ---------------- launch ----------------------------------------------------
extern "C" void kernel_launch(void* const* d_in, const int* in_sizes, int n_in,
                              void* d_out, int out_size) {
    const float* x    = (const float*)d_in[0];
    const float* cosb = (const float*)d_in[1];
    const float* sinb = (const float*)d_in[2];
    const float* ln1  = (const float*)d_in[3];
    const float* ln2  = (const float*)d_in[4];
    const float* Wq   = (const float*)d_in[5];
    const float* Wk   = (const float*)d_in[6];
    const float* Wv   = (const float*)d_in[7];
    const float* Wo   = (const float*)d_in[8];
    const float* Wr   = (const float*)d_in[9];
    const float* Wg   = (const float*)d_in[10];
    const float* Wu   = (const float*)d_in[11];
    const float* Wd   = (const float*)d_in[12];
    float* out = (float*)d_out;
    float* rl  = out + (size_t)NTOK * HDIM;

    float *h, *q, *k, *v, *ao, *f, *gb, *es;
    int *cnt, *el;
    cudaGetSymbolAddress((void**)&h,   g_h);
    cudaGetSymbolAddress((void**)&q,   g_q);
    cudaGetSymbolAddress((void**)&k,   g_k);
    cudaGetSymbolAddress((void**)&v,   g_v);
    cudaGetSymbolAddress((void**)&ao,  g_ao);
    cudaGetSymbolAddress((void**)&f,   g_f);
    cudaGetSymbolAddress((void**)&gb,  g_gbuf);
    cudaGetSymbolAddress((void**)&es,  g_escore);
    cudaGetSymbolAddress((void**)&cnt, g_cnt);
    cudaGetSymbolAddress((void**)&el,  g_elist);

    const int ATTN_SMEM = (2 * 64 * 65 + 64 * 68 + 64 * 65) * 4;
    cudaFuncSetAttribute(attn_kernel, cudaFuncAttributeMaxDynamicSharedMemorySize,
                         ATTN_SMEM);
    cudaFuncSetAttribute(mma_gemm<0>, cudaFuncAttributeMaxDynamicSharedMemorySize, GEMM_SMEM);
    cudaFuncSetAttribute(mma_gemm<1>, cudaFuncAttributeMaxDynamicSharedMemorySize, GEMM_SMEM);
    cudaFuncSetAttribute(mma_gemm<2>, cudaFuncAttributeMaxDynamicSharedMemorySize, GEMM_SMEM);
    cudaFuncSetAttribute(mma_gemm<3>, cudaFuncAttributeMaxDynamicSharedMemorySize, GEMM_SMEM);
    cudaFuncSetAttribute(mma_gemm<4>, cudaFuncAttributeMaxDynamicSharedMemorySize, GEMM_SMEM);

    // 1. h = rmsnorm(x, ln1_w)  [tf32 + permuted]
    rmsnorm_kernel<<<NTOK, 256>>>(x, ln1, h);
    // 2. fused QKV projection (192 blocks)
    mma_gemm<4><<<dim3(12, 16), 256, GEMM_SMEM>>>(h, Wq, nullptr, q, NTOK, 1536, 1024,
                                                  nullptr, nullptr, nullptr, Wk, Wv, k, v);
    // 3. RoPE
    rope_kernel<<<(NTOK * NHEAD * 32 + 255) / 256, 256>>>(q, cosb, sinb, NHEAD);
    rope_kernel<<<(NTOK * NKVH  * 32 + 255) / 256, 256>>>(k, cosb, sinb, NKVH);
    // 4. attention (output tf32 + permuted)
    attn_kernel<<<dim3(TSEQ / 64, NHEAD, BATCH), 256, ATTN_SMEM>>>(q, k, v, ao);
    // 5. x1 = x + ao@Wo
    mma_gemm<0><<<dim3(8, 16), 256, GEMM_SMEM>>>(ao, Wo, x, out, NTOK, 1024, 1024,
                                                 nullptr, nullptr, nullptr, nullptr, nullptr, nullptr, nullptr);
    // 6. f = rmsnorm(x1, ln2_w)  [tf32 + permuted]
    rmsnorm_kernel<<<NTOK, 256>>>(out, ln2, f);
    // 7. router logits
    mma_gemm<0><<<dim3(1, 16), 256, GEMM_SMEM>>>(f, Wr, nullptr, rl, NTOK, NEXP, 1024,
                                                 nullptr, nullptr, nullptr, nullptr, nullptr, nullptr, nullptr);
    // 8-9. top-k + expert lists
    zero_cnt_kernel<<<1, 64>>>(cnt);
    router_topk_kernel<<<NTOK / 256, 256>>>(rl, cnt, el, es);
    // 10a. gate GEMM -> gbuf (plain)
    mma_gemm<1><<<dim3(IDIM / 128, NTOK / 128, NEXP), 256, GEMM_SMEM>>>(f, Wg, nullptr, gb, NTOK, IDIM, 1024,
                                                 cnt, el, es, nullptr, nullptr, nullptr, nullptr);
    // 10b. up GEMM, fused silu(gate)*up*score -> gbuf (tf32 + permuted)
    mma_gemm<2><<<dim3(IDIM / 128, NTOK / 128, NEXP), 256, GEMM_SMEM>>>(f, Wu, nullptr, gb, NTOK, IDIM, 1024,
                                                 cnt, el, es, nullptr, nullptr, nullptr, nullptr);
    // 11. down GEMM + scatter-add onto residual in d_out
    mma_gemm<3><<<dim3(HDIM / 128, NTOK / 128, NEXP), 256, GEMM_SMEM>>>(gb, Wd, nullptr, out, NTOK, HDIM, IDIM,
                                                 cnt, el, es, nullptr, nullptr, nullptr, nullptr);
}